// round 8
// baseline (speedup 1.0000x reference)
#include <cuda_runtime.h>
#include <math.h>
#include <stdint.h>

#define FULLM 0xffffffffu
#define BMAX 64
#define TMAX 1000
#define UPAD 256

// Scratch (allocation-free rule: __device__ globals).
__device__ float g_loss[BMAX];
__device__ float g_logZ[BMAX * TMAX];
__device__ int   g_done;
__device__ float g_r[(size_t)BMAX * TMAX * UPAD];   // 64 MB, permuted layout

// ---------------------------------------------------------------------------
// Phase 1: r[b,t,u] = exp(x+1) (masked for u>=tl); logZ = log1p(sum r) - 1.
// One warp per (b,t) row; PERMUTED store: lane's 8 floats at slots lane, 32+lane.
// Thread (0,0) also resets the completion ticket for the scan kernel.
// ---------------------------------------------------------------------------
__global__ void __launch_bounds__(256)
fsloss_prep(const float* __restrict__ attn, const int* __restrict__ text_lens,
            int B, int T, int U)
{
    if (blockIdx.x == 0 && threadIdx.x == 0) g_done = 0;

    const int gw   = (blockIdx.x * blockDim.x + threadIdx.x) >> 5;
    const int lane = threadIdx.x & 31;
    if (gw >= B * T) return;
    const int b  = gw / T;
    const int tl = text_lens[b];
    const int u0 = 8 * lane;

    const float2* x2 = (const float2*)(attn + (size_t)gw * U) + 4 * lane;
    float v[8];
    #pragma unroll
    for (int j = 0; j < 4; ++j) {
        float2 d = make_float2(0.f, 0.f);
        if (u0 + 2 * j + 1 < U) d = __ldg(&x2[j]);
        v[2 * j]     = d.x;
        v[2 * j + 1] = d.y;
    }
    float s = 0.f;
    #pragma unroll
    for (int k = 0; k < 8; ++k) {
        float e = (u0 + k < tl) ? __expf(v[k] + 1.f) : 0.f;  // r = exp(x+1)
        v[k] = e;
        s += e;
    }
    #pragma unroll
    for (int off = 16; off; off >>= 1) s += __shfl_xor_sync(FULLM, s, off);
    if (lane == 0) g_logZ[gw] = __logf(s + 1.f) - 1.f;  // log(e^-1 + sum exp x)

    float4* dst = (float4*)(g_r + (size_t)gw * UPAD);
    dst[lane]      = make_float4(v[0], v[1], v[2], v[3]);
    dst[32 + lane] = make_float4(v[4], v[5], v[6], v[7]);
}

// ---------------------------------------------------------------------------
// Phase 2: one WARP per batch. 512 states: lane l holds e[k]=b[16l+2k],
// o[k]=b[16l+2k+1]. new_e = e + o_prev; new_o = r*(o + e + o_prev).
// Pipelined shuffle: k=7 computed first, shfl for the NEXT step issued early,
// prev consumed at k=0 placed last -> shfl latency fully hidden.
// ---------------------------------------------------------------------------
__device__ __forceinline__ void fs_step_pipe(float e[8], float o[8],
                                             float4 r0, float4 r1,
                                             float prevS, float& rawNext)
{
    const float r[8] = {r0.x, r0.y, r0.z, r0.w, r1.x, r1.y, r1.z, r1.w};
    // k = 7 first (old e7, o6, o7); shfl for the next step issued immediately
    float s7  = e[7] + o[6];
    float t7  = o[7] + s7;
    float o7n = r[7] * t7;
    rawNext = __shfl_up_sync(FULLM, o7n, 1);
    // k = 6..1 descending (reads old o[k-1], writes o[k] already consumed)
    #pragma unroll
    for (int k = 6; k >= 1; --k) {
        float s = e[k] + o[k - 1];
        float t = o[k] + s;
        e[k] = s;
        o[k] = r[k] * t;
    }
    // k = 0 last: prevS (shuffled during the PREVIOUS step) is ready by now
    float s0 = e[0] + prevS;
    float t0 = o[0] + s0;
    e[0] = s0;
    o[0] = r[0] * t0;
    e[7] = s7; o[7] = o7n;
}

// simple step (shfl at head) for the short tail
__device__ __forceinline__ void fs_step(float e[8], float o[8],
                                        float4 r0, float4 r1, float f)
{
    float prev = __shfl_up_sync(FULLM, o[7], 1) * f;
    const float r[8] = {r0.x, r0.y, r0.z, r0.w, r1.x, r1.y, r1.z, r1.w};
    #pragma unroll
    for (int k = 0; k < 8; ++k) {
        float s = e[k] + prev;
        float t = o[k] + s;
        prev = o[k];
        e[k] = s;
        o[k] = r[k] * t;
    }
}

#define FS_RENORM()                                                           \
    do {                                                                      \
        float me = fmaxf(fmaxf(fmaxf(e[0], e[1]), fmaxf(e[2], e[3])),         \
                         fmaxf(fmaxf(e[4], e[5]), fmaxf(e[6], e[7])));        \
        float mo = fmaxf(fmaxf(fmaxf(o[0], o[1]), fmaxf(o[2], o[3])),         \
                         fmaxf(fmaxf(o[4], o[5]), fmaxf(o[6], o[7])));        \
        float m = fmaxf(me, mo);                                              \
        bool nz = (m > 0.f);                                                  \
        if (nz) {                                                             \
            int Ee = (int)((__float_as_uint(m) >> 23) & 255u);                \
            float sc = __uint_as_float((unsigned)(254 - Ee) << 23);           \
            _Pragma("unroll")                                                 \
            for (int j = 0; j < 8; ++j) { e[j] *= sc; o[j] *= sc; }           \
            G += Ee - 127;                                                    \
        }                                                                     \
        int val = (G << 1) | (nz ? 1 : 0);                                    \
        int up  = __shfl_up_sync(FULLM, val, 1);                              \
        int Gup = up >> 1;                                                    \
        if (!nz && lane > 0) G = Gup;                                         \
        int D = Gup - G;                                                      \
        if (D > 127) D = 127;                                                 \
        f = (lane == 0 || D < -126) ? 0.f                                     \
            : __uint_as_float((unsigned)(D + 127) << 23);                     \
    } while (0)

// capture states S (even, e[k] at 16l+2k==S) and S-1 (odd, o[k] at 16l+2k==S-2)
#define FS_CAPTURE()                                                          \
    do {                                                                      \
        _Pragma("unroll")                                                     \
        for (int k = 0; k < 8; ++k) {                                         \
            int se_ = 16 * lane + 2 * k;                                      \
            if (se_ == S)     fincap += e[k];                                 \
            if (se_ == S - 2) fincap += o[k];                                 \
        }                                                                     \
        Gcap = G;                                                             \
    } while (0)

__global__ void __launch_bounds__(32)
fsloss_scan(const int* __restrict__ text_lens, const int* __restrict__ mel_lens,
            int T, float* __restrict__ out)
{
    const int b = blockIdx.x, lane = threadIdx.x;
    const int tl = text_lens[b], ml = mel_lens[b];
    const int S = 2 * tl, mlm1 = ml - 1;
    const int B = gridDim.x;
    const float4* P  = (const float4*)(g_r + (size_t)b * T * UPAD);
    const float4* p0 = P + lane;        // permuted: slot lane
    const float4* p1 = P + 32 + lane;   // permuted: slot 32+lane

    float e[8], o[8];
    #pragma unroll
    for (int j = 0; j < 8; ++j) { e[j] = 0.f; o[j] = 0.f; }
    if (lane == 0) e[0] = 1.f;          // state 0

    int   G = 0, Gcap = 0;
    float fincap = 0.f;
    float f = (lane == 0) ? 0.f : 1.f;

    // two 8-row buffer sets; 16 rows in flight
    float4 Ax[8], Ay[8], Bx[8], By[8];
    #pragma unroll
    for (int r = 0; r < 8; ++r) { Ax[r] = __ldg(p0 + r * 64);
                                  Ay[r] = __ldg(p1 + r * 64); }
    #pragma unroll
    for (int r = 0; r < 8; ++r) { Bx[r] = __ldg(p0 + (r + 8) * 64);
                                  By[r] = __ldg(p1 + (r + 8) * 64); }

    const int full = mlm1 >> 4;          // complete 16-step superblocks
    float prevS = 0.f, raw;              // o is all-zero initially

    for (int i = 0; i < full; ++i) {
        #pragma unroll
        for (int r = 0; r < 8; ++r) {
            fs_step_pipe(e, o, Ax[r], Ay[r], prevS, raw);
            prevS = raw * f;
        }
        {   // reload A <- rows 16(i+1)..+7 (clamped rows are never consumed)
            int rb = 16 * (i + 1); if (rb > T - 8) rb = T - 8;
            const float4* qa0 = P + (size_t)rb * 64 + lane;
            const float4* qa1 = qa0 + 32;
            #pragma unroll
            for (int r = 0; r < 8; ++r) { Ax[r] = __ldg(qa0 + r * 64);
                                          Ay[r] = __ldg(qa1 + r * 64); }
        }
        FS_RENORM();
        prevS = __shfl_up_sync(FULLM, o[7], 1) * f;   // post-scale refresh
        #pragma unroll
        for (int r = 0; r < 8; ++r) {
            fs_step_pipe(e, o, Bx[r], By[r], prevS, raw);
            prevS = raw * f;
        }
        {   // reload B <- rows 16(i+1)+8..+15
            int rb = 16 * (i + 1) + 8; if (rb > T - 8) rb = T - 8;
            const float4* qb0 = P + (size_t)rb * 64 + lane;
            const float4* qb1 = qb0 + 32;
            #pragma unroll
            for (int r = 0; r < 8; ++r) { Bx[r] = __ldg(qb0 + r * 64);
                                          By[r] = __ldg(qb1 + r * 64); }
        }
        FS_RENORM();
        prevS = __shfl_up_sync(FULLM, o[7], 1) * f;   // post-scale refresh
    }

    // tail: steps 16*full .. mlm1 (1..16 steps); rows resident in A/B.
    {
        const int rem = mlm1 - 16 * full;   // 0..15
        #pragma unroll
        for (int r = 0; r < 16; ++r) {
            float4 t0 = (r < 8) ? Ax[r & 7] : Bx[r & 7];
            float4 t1 = (r < 8) ? Ay[r & 7] : By[r & 7];
            fs_step(e, o, t0, t1, f);
            if (r == rem) { FS_CAPTURE(); break; }
            if (r == 7) FS_RENORM();
        }
    }

    // epilogue: Zsum = sum_{t<ml} logZ_t  (log c = -ml - Zsum)
    const float* lz = g_logZ + (size_t)b * T;
    double zs = 0.0, zs2 = 0.0;
    int i2 = lane;
    for (; i2 + 32 < ml; i2 += 64) {
        zs  += (double)__ldg(&lz[i2]);
        zs2 += (double)__ldg(&lz[i2 + 32]);
    }
    if (i2 < ml) zs += (double)__ldg(&lz[i2]);
    zs += zs2;
    #pragma unroll
    for (int off = 16; off; off >>= 1)
        zs += __shfl_xor_sync(FULLM, zs, off);

    // lse over lanes (up to 2 lanes hold fin terms with different exponents)
    double lv = (fincap > 0.f)
        ? (log((double)fincap) + (double)Gcap * 0.6931471805599453)
        : -1e300;
    double mx = lv;
    #pragma unroll
    for (int off = 16; off; off >>= 1)
        mx = fmax(mx, __shfl_xor_sync(FULLM, mx, off));
    double ex = (lv > -1e299) ? exp(lv - mx) : 0.0;
    #pragma unroll
    for (int off = 16; off; off >>= 1)
        ex += __shfl_xor_sync(FULLM, ex, off);

    if (lane == 0) {
        float loss = 0.f;
        if (mx > -1e299) {
            double fin = (mx + log(ex)) - (double)ml - zs;
            loss = (float)(-fin / (double)tl);
        }
        g_loss[b] = loss;
        __threadfence();
        int ticket = atomicAdd(&g_done, 1);
        if (ticket == B - 1) {           // last CTA reduces (fixed order)
            float s = 0.f;
            for (int i = 0; i < B; ++i) s += g_loss[i];
            out[0] = s / (float)B;
        }
    }
}

extern "C" void kernel_launch(void* const* d_in, const int* in_sizes, int n_in,
                              void* d_out, int out_size)
{
    const float* attn = (const float*)d_in[0];
    const int*   tl   = (const int*)d_in[1];
    const int*   ml   = (const int*)d_in[2];
    int B = in_sizes[1];
    const int U = 250;
    int T = in_sizes[0] / (B * U);

    int rows = B * T;
    fsloss_prep<<<(rows * 32 + 255) / 256, 256>>>(attn, tl, B, T, U);
    fsloss_scan<<<B, 32>>>(tl, ml, T, (float*)d_out);
}

// round 9
// speedup vs baseline: 1.0256x; 1.0256x over previous
#include <cuda_runtime.h>
#include <math.h>
#include <stdint.h>

#define FULLM 0xffffffffu
#define BMAX 64
#define TMAX 1000
#define UPAD 256

typedef unsigned long long ull;

// Scratch (allocation-free rule: __device__ globals).
__device__ float g_loss[BMAX];
__device__ float g_logZ[BMAX * TMAX];
__device__ int   g_done;
__device__ float g_r[(size_t)BMAX * TMAX * UPAD];   // 64 MB, permuted layout

// ---- f32x2 packed helpers (Blackwell sm_103a) ------------------------------
__device__ __forceinline__ ull addx2(ull a, ull b) {
    ull r; asm("add.rn.f32x2 %0, %1, %2;" : "=l"(r) : "l"(a), "l"(b)); return r;
}
__device__ __forceinline__ ull mulx2(ull a, ull b) {
    ull r; asm("mul.rn.f32x2 %0, %1, %2;" : "=l"(r) : "l"(a), "l"(b)); return r;
}
__device__ __forceinline__ ull packx2(float lo, float hi) {
    ull r; asm("mov.b64 %0, {%1, %2};" : "=l"(r) : "f"(lo), "f"(hi)); return r;
}
__device__ __forceinline__ float lox2(ull v) {
    float a, b; asm("mov.b64 {%0, %1}, %2;" : "=f"(a), "=f"(b) : "l"(v)); return a;
}
__device__ __forceinline__ float hix2(ull v) {
    float a, b; asm("mov.b64 {%0, %1}, %2;" : "=f"(a), "=f"(b) : "l"(v)); return b;
}

// ---------------------------------------------------------------------------
// Phase 1: r[b,t,u] = exp(x+1) (masked for u>=tl); logZ = log1p(sum r) - 1.
// PERMUTED + INTERLEAVED store: lane's 8 values stored as
// [v0,v4,v1,v5] at slot lane, [v2,v6,v3,v7] at slot 32+lane  (stride-4 pairs).
// ---------------------------------------------------------------------------
__global__ void __launch_bounds__(256)
fsloss_prep(const float* __restrict__ attn, const int* __restrict__ text_lens,
            int B, int T, int U)
{
    if (blockIdx.x == 0 && threadIdx.x == 0) g_done = 0;

    const int gw   = (blockIdx.x * blockDim.x + threadIdx.x) >> 5;
    const int lane = threadIdx.x & 31;
    if (gw >= B * T) return;
    const int b  = gw / T;
    const int tl = text_lens[b];
    const int u0 = 8 * lane;

    const float2* x2 = (const float2*)(attn + (size_t)gw * U) + 4 * lane;
    float v[8];
    #pragma unroll
    for (int j = 0; j < 4; ++j) {
        float2 d = make_float2(0.f, 0.f);
        if (u0 + 2 * j + 1 < U) d = __ldg(&x2[j]);
        v[2 * j]     = d.x;
        v[2 * j + 1] = d.y;
    }
    float s = 0.f;
    #pragma unroll
    for (int k = 0; k < 8; ++k) {
        float e = (u0 + k < tl) ? __expf(v[k] + 1.f) : 0.f;  // r = exp(x+1)
        v[k] = e;
        s += e;
    }
    #pragma unroll
    for (int off = 16; off; off >>= 1) s += __shfl_xor_sync(FULLM, s, off);
    if (lane == 0) g_logZ[gw] = __logf(s + 1.f) - 1.f;

    float4* dst = (float4*)(g_r + (size_t)gw * UPAD);
    dst[lane]      = make_float4(v[0], v[4], v[1], v[5]);   // pairs (r0,r4),(r1,r5)
    dst[32 + lane] = make_float4(v[2], v[6], v[3], v[7]);   // pairs (r2,r6),(r3,r7)
}

// ---------------------------------------------------------------------------
// Phase 2: one WARP per batch. Lane l holds states 16l..16l+15 as packed pairs
// E[j]=(e[j],e[j+4]), O[j]=(o[j],o[j+4]).  Shifted operand (o[j-1],o[j+3]) is
// exactly O[j-1] for j>=1; j=0 needs one pack(prev, o3).  12 packed fma/step.
// ---------------------------------------------------------------------------
__device__ __forceinline__ void stepP(ull E[4], ull O[4],
                                      ulonglong2 Rlo, ulonglong2 Rhi,
                                      float prevS, float& rawNext)
{
    float o3lo = lox2(O[3]);                   // old o[3], saved before overwrite
    ull S3 = addx2(E[3], O[2]);
    ull T3 = addx2(O[3], S3);
    ull O3n = mulx2(Rhi.y, T3);
    rawNext = __shfl_up_sync(FULLM, hix2(O3n), 1);   // new o[7] -> next step
    ull S2 = addx2(E[2], O[1]);
    ull T2 = addx2(O[2], S2);
    O[2] = mulx2(Rhi.x, T2); E[2] = S2;
    ull S1 = addx2(E[1], O[0]);
    ull T1 = addx2(O[1], S1);
    O[1] = mulx2(Rlo.y, T1); E[1] = S1;
    ull Osh0 = packx2(prevS, o3lo);            // prevS consumed LAST (hidden shfl)
    ull S0 = addx2(E[0], Osh0);
    ull T0 = addx2(O[0], S0);
    O[0] = mulx2(Rlo.x, T0); E[0] = S0;
    O[3] = O3n; E[3] = S3;
}

// simple packed step (shfl at head) for the short tail
__device__ __forceinline__ void stepS(ull E[4], ull O[4],
                                      ulonglong2 Rlo, ulonglong2 Rhi, float f)
{
    float prev = __shfl_up_sync(FULLM, hix2(O[3]), 1) * f;
    float o3lo = lox2(O[3]);
    ull S3 = addx2(E[3], O[2]); ull T3 = addx2(O[3], S3);
    O[3] = mulx2(Rhi.y, T3); E[3] = S3;
    ull S2 = addx2(E[2], O[1]); ull T2 = addx2(O[2], S2);
    O[2] = mulx2(Rhi.x, T2); E[2] = S2;
    ull S1 = addx2(E[1], O[0]); ull T1 = addx2(O[1], S1);
    O[1] = mulx2(Rlo.y, T1); E[1] = S1;
    ull Osh0 = packx2(prev, o3lo);
    ull S0 = addx2(E[0], Osh0); ull T0 = addx2(O[0], S0);
    O[0] = mulx2(Rlo.x, T0); E[0] = S0;
}

#define FS_RENORM()                                                           \
    do {                                                                      \
        float m = fmaxf(                                                      \
            fmaxf(fmaxf(lox2(E[0]), hix2(E[0])), fmaxf(lox2(E[1]), hix2(E[1]))), \
            fmaxf(fmaxf(lox2(E[2]), hix2(E[2])), fmaxf(lox2(E[3]), hix2(E[3])))); \
        float mo = fmaxf(                                                     \
            fmaxf(fmaxf(lox2(O[0]), hix2(O[0])), fmaxf(lox2(O[1]), hix2(O[1]))), \
            fmaxf(fmaxf(lox2(O[2]), hix2(O[2])), fmaxf(lox2(O[3]), hix2(O[3])))); \
        m = fmaxf(m, mo);                                                     \
        bool nz = (m > 0.f);                                                  \
        if (nz) {                                                             \
            int Ee = (int)((__float_as_uint(m) >> 23) & 255u);                \
            float sc = __uint_as_float((unsigned)(254 - Ee) << 23);           \
            ull SC = packx2(sc, sc);                                          \
            E[0] = mulx2(E[0], SC); E[1] = mulx2(E[1], SC);                   \
            E[2] = mulx2(E[2], SC); E[3] = mulx2(E[3], SC);                   \
            O[0] = mulx2(O[0], SC); O[1] = mulx2(O[1], SC);                   \
            O[2] = mulx2(O[2], SC); O[3] = mulx2(O[3], SC);                   \
            G += Ee - 127;                                                    \
        }                                                                     \
        int val = (G << 1) | (nz ? 1 : 0);                                    \
        int up  = __shfl_up_sync(FULLM, val, 1);                              \
        int Gup = up >> 1;                                                    \
        if (!nz && lane > 0) G = Gup;                                         \
        int D = Gup - G;                                                      \
        if (D > 127) D = 127;                                                 \
        f = (lane == 0 || D < -126) ? 0.f                                     \
            : __uint_as_float((unsigned)(D + 127) << 23);                     \
    } while (0)

// capture states S (even) and S-1 (odd, via o at state index S-2)
#define FS_CAPTURE()                                                          \
    do {                                                                      \
        _Pragma("unroll")                                                     \
        for (int k = 0; k < 8; ++k) {                                         \
            float ek = (k < 4) ? lox2(E[k]) : hix2(E[k - 4]);                 \
            float ok = (k < 4) ? lox2(O[k]) : hix2(O[k - 4]);                 \
            int se_ = 16 * lane + 2 * k;                                      \
            if (se_ == S)     fincap += ek;                                   \
            if (se_ == S - 2) fincap += ok;                                   \
        }                                                                     \
        Gcap = G;                                                             \
    } while (0)

__global__ void __launch_bounds__(32)
fsloss_scan(const int* __restrict__ text_lens, const int* __restrict__ mel_lens,
            int T, float* __restrict__ out)
{
    const int b = blockIdx.x, lane = threadIdx.x;
    const int tl = text_lens[b], ml = mel_lens[b];
    const int S = 2 * tl, mlm1 = ml - 1;
    const int B = gridDim.x;
    const ulonglong2* P  = (const ulonglong2*)(g_r + (size_t)b * T * UPAD);
    const ulonglong2* p0 = P + lane;        // chunk 0: pairs R[0],R[1]
    const ulonglong2* p1 = P + 32 + lane;   // chunk 1: pairs R[2],R[3]

    ull E[4], O[4];
    #pragma unroll
    for (int j = 0; j < 4; ++j) { E[j] = 0ull; O[j] = 0ull; }
    if (lane == 0) E[0] = packx2(1.f, 0.f);   // state 0 = 1

    int   G = 0, Gcap = 0;
    float fincap = 0.f;
    float f = (lane == 0) ? 0.f : 1.f;

    ulonglong2 Ax[8], Ay[8], Bx[8], By[8];
    #pragma unroll
    for (int r = 0; r < 8; ++r) { Ax[r] = __ldg(p0 + r * 64);
                                  Ay[r] = __ldg(p1 + r * 64); }
    #pragma unroll
    for (int r = 0; r < 8; ++r) { Bx[r] = __ldg(p0 + (r + 8) * 64);
                                  By[r] = __ldg(p1 + (r + 8) * 64); }

    const int full = mlm1 >> 4;          // complete 16-step superblocks
    float prevS = 0.f, raw;

    for (int i = 0; i < full; ++i) {
        {   // consume A, reload A <- rows 16(i+1).. interleaved 2 LDG/step
            int rb = 16 * (i + 1); if (rb > T - 8) rb = T - 8;
            const ulonglong2* qa0 = P + (size_t)rb * 64 + lane;
            const ulonglong2* qa1 = qa0 + 32;
            #pragma unroll
            for (int r = 0; r < 8; ++r) {
                stepP(E, O, Ax[r], Ay[r], prevS, raw);
                prevS = raw * f;
                Ax[r] = __ldg(qa0 + r * 64);
                Ay[r] = __ldg(qa1 + r * 64);
            }
        }
        FS_RENORM();
        prevS = __shfl_up_sync(FULLM, hix2(O[3]), 1) * f;   // post-scale refresh
        {   // consume B, reload B <- rows 16(i+1)+8..
            int rb = 16 * (i + 1) + 8; if (rb > T - 8) rb = T - 8;
            const ulonglong2* qb0 = P + (size_t)rb * 64 + lane;
            const ulonglong2* qb1 = qb0 + 32;
            #pragma unroll
            for (int r = 0; r < 8; ++r) {
                stepP(E, O, Bx[r], By[r], prevS, raw);
                prevS = raw * f;
                Bx[r] = __ldg(qb0 + r * 64);
                By[r] = __ldg(qb1 + r * 64);
            }
        }
        FS_RENORM();
        prevS = __shfl_up_sync(FULLM, hix2(O[3]), 1) * f;
    }

    // tail: steps 16*full .. mlm1 (1..16 steps); rows resident in A/B.
    {
        const int rem = mlm1 - 16 * full;   // 0..15
        #pragma unroll
        for (int r = 0; r < 16; ++r) {
            ulonglong2 t0 = (r < 8) ? Ax[r & 7] : Bx[r & 7];
            ulonglong2 t1 = (r < 8) ? Ay[r & 7] : By[r & 7];
            stepS(E, O, t0, t1, f);
            if (r == rem) { FS_CAPTURE(); break; }
            if (r == 7) FS_RENORM();
        }
    }

    // epilogue: Zsum = sum_{t<ml} logZ_t  (log c = -ml - Zsum)
    const float* lz = g_logZ + (size_t)b * T;
    double zs = 0.0, zs2 = 0.0;
    int i2 = lane;
    for (; i2 + 32 < ml; i2 += 64) {
        zs  += (double)__ldg(&lz[i2]);
        zs2 += (double)__ldg(&lz[i2 + 32]);
    }
    if (i2 < ml) zs += (double)__ldg(&lz[i2]);
    zs += zs2;
    #pragma unroll
    for (int off = 16; off; off >>= 1)
        zs += __shfl_xor_sync(FULLM, zs, off);

    // lse over lanes (up to 2 lanes hold fin terms with different exponents)
    double lv = (fincap > 0.f)
        ? (log((double)fincap) + (double)Gcap * 0.6931471805599453)
        : -1e300;
    double mx = lv;
    #pragma unroll
    for (int off = 16; off; off >>= 1)
        mx = fmax(mx, __shfl_xor_sync(FULLM, mx, off));
    double ex = (lv > -1e299) ? exp(lv - mx) : 0.0;
    #pragma unroll
    for (int off = 16; off; off >>= 1)
        ex += __shfl_xor_sync(FULLM, ex, off);

    if (lane == 0) {
        float loss = 0.f;
        if (mx > -1e299) {
            double fin = (mx + log(ex)) - (double)ml - zs;
            loss = (float)(-fin / (double)tl);
        }
        g_loss[b] = loss;
        __threadfence();
        int ticket = atomicAdd(&g_done, 1);
        if (ticket == B - 1) {           // last CTA reduces (fixed order)
            float s = 0.f;
            for (int i = 0; i < B; ++i) s += g_loss[i];
            out[0] = s / (float)B;
        }
    }
}

extern "C" void kernel_launch(void* const* d_in, const int* in_sizes, int n_in,
                              void* d_out, int out_size)
{
    const float* attn = (const float*)d_in[0];
    const int*   tl   = (const int*)d_in[1];
    const int*   ml   = (const int*)d_in[2];
    int B = in_sizes[1];
    const int U = 250;
    int T = in_sizes[0] / (B * U);

    int rows = B * T;
    fsloss_prep<<<(rows * 32 + 255) / 256, 256>>>(attn, tl, B, T, U);
    fsloss_scan<<<B, 32>>>(tl, ml, T, (float*)d_out);
}

// round 10
// speedup vs baseline: 1.2826x; 1.2505x over previous
#include <cuda_runtime.h>
#include <math.h>
#include <stdint.h>

#define FULLM 0xffffffffu
#define BMAX 64
#define TMAX 1000
#define UPAD 256

typedef unsigned long long ull;

// Scratch (allocation-free rule: __device__ globals).
__device__ float g_loss[BMAX];
__device__ float g_logZ[BMAX * TMAX];
__device__ int   g_done;
__device__ __align__(128) float g_r[(size_t)BMAX * TMAX * UPAD];  // 64 MB

// ---- f32x2 packed helpers (Blackwell sm_103a) ------------------------------
__device__ __forceinline__ ull addx2(ull a, ull b) {
    ull r; asm("add.rn.f32x2 %0, %1, %2;" : "=l"(r) : "l"(a), "l"(b)); return r;
}
__device__ __forceinline__ ull mulx2(ull a, ull b) {
    ull r; asm("mul.rn.f32x2 %0, %1, %2;" : "=l"(r) : "l"(a), "l"(b)); return r;
}
__device__ __forceinline__ ull packx2(float lo, float hi) {
    ull r; asm("mov.b64 %0, {%1, %2};" : "=l"(r) : "f"(lo), "f"(hi)); return r;
}
__device__ __forceinline__ float lox2(ull v) {
    float a, b; asm("mov.b64 {%0, %1}, %2;" : "=f"(a), "=f"(b) : "l"(v)); return a;
}
__device__ __forceinline__ float hix2(ull v) {
    float a, b; asm("mov.b64 {%0, %1}, %2;" : "=f"(a), "=f"(b) : "l"(v)); return b;
}
__device__ __forceinline__ uint32_t smem_u32(const void* p) {
    uint32_t a;
    asm("{.reg .u64 t; cvta.to.shared.u64 t, %1; cvt.u32.u64 %0, t;}"
        : "=r"(a) : "l"(p));
    return a;
}
__device__ __forceinline__ ulonglong2 lds128(uint32_t a) {
    ulonglong2 v;
    asm("ld.shared.v2.u64 {%0, %1}, [%2];" : "=l"(v.x), "=l"(v.y) : "r"(a));
    return v;
}
__device__ __forceinline__ void mbar_wait(uint32_t bar, int parity) {
    asm volatile(
        "{\n\t.reg .pred P;\n"
        "W%=:\n\t"
        "mbarrier.try_wait.parity.shared.b64 P, [%0], %1;\n\t"
        "@!P bra W%=;\n\t}"
        :: "r"(bar), "r"(parity) : "memory");
}
__device__ __forceinline__ void tma_fill(uint32_t dst, const float* src,
                                         uint32_t bar) {
    asm volatile("mbarrier.arrive.expect_tx.shared.b64 _, [%0], %1;"
                 :: "r"(bar), "r"(8192) : "memory");
    asm volatile(
        "cp.async.bulk.shared::cta.global.mbarrier::complete_tx::bytes "
        "[%0], [%1], %2, [%3];"
        :: "r"(dst), "l"(src), "r"(8192), "r"(bar) : "memory");
}

// ---------------------------------------------------------------------------
// Phase 1: r[b,t,u] = exp(x+1) (masked for u>=tl); logZ = log1p(sum r) - 1.
// PERMUTED + INTERLEAVED store: [v0,v4,v1,v5] at slot lane, [v2,v6,v3,v7] at
// slot 32+lane (stride-4 pairs for the packed scan).
// ---------------------------------------------------------------------------
__global__ void __launch_bounds__(256)
fsloss_prep(const float* __restrict__ attn, const int* __restrict__ text_lens,
            int B, int T, int U)
{
    if (blockIdx.x == 0 && threadIdx.x == 0) g_done = 0;

    const int gw   = (blockIdx.x * blockDim.x + threadIdx.x) >> 5;
    const int lane = threadIdx.x & 31;
    if (gw >= B * T) return;
    const int b  = gw / T;
    const int tl = text_lens[b];
    const int u0 = 8 * lane;

    const float2* x2 = (const float2*)(attn + (size_t)gw * U) + 4 * lane;
    float v[8];
    #pragma unroll
    for (int j = 0; j < 4; ++j) {
        float2 d = make_float2(0.f, 0.f);
        if (u0 + 2 * j + 1 < U) d = __ldg(&x2[j]);
        v[2 * j]     = d.x;
        v[2 * j + 1] = d.y;
    }
    float s = 0.f;
    #pragma unroll
    for (int k = 0; k < 8; ++k) {
        float e = (u0 + k < tl) ? __expf(v[k] + 1.f) : 0.f;  // r = exp(x+1)
        v[k] = e;
        s += e;
    }
    #pragma unroll
    for (int off = 16; off; off >>= 1) s += __shfl_xor_sync(FULLM, s, off);
    if (lane == 0) g_logZ[gw] = __logf(s + 1.f) - 1.f;

    float4* dst = (float4*)(g_r + (size_t)gw * UPAD);
    dst[lane]      = make_float4(v[0], v[4], v[1], v[5]);
    dst[32 + lane] = make_float4(v[2], v[6], v[3], v[7]);
}

// ---------------------------------------------------------------------------
// Phase 2 step: lane l holds packed pairs E[j]=(e[j],e[j+4]), O[j]=(o[j],o[j+4]).
// Shifted operand (o[j-1],o[j+3]) is exactly O[j-1] for j>=1.
// ---------------------------------------------------------------------------
__device__ __forceinline__ void stepP(ull E[4], ull O[4],
                                      ulonglong2 Rlo, ulonglong2 Rhi,
                                      float prevS, float& rawNext)
{
    float o3lo = lox2(O[3]);
    ull S3 = addx2(E[3], O[2]);
    ull T3 = addx2(O[3], S3);
    ull O3n = mulx2(Rhi.y, T3);
    rawNext = __shfl_up_sync(FULLM, hix2(O3n), 1);   // new o[7] -> next step
    ull S2 = addx2(E[2], O[1]);
    ull T2 = addx2(O[2], S2);
    O[2] = mulx2(Rhi.x, T2); E[2] = S2;
    ull S1 = addx2(E[1], O[0]);
    ull T1 = addx2(O[1], S1);
    O[1] = mulx2(Rlo.y, T1); E[1] = S1;
    ull Osh0 = packx2(prevS, o3lo);                  // prevS consumed last
    ull S0 = addx2(E[0], Osh0);
    ull T0 = addx2(O[0], S0);
    O[0] = mulx2(Rlo.x, T0); E[0] = S0;
    O[3] = O3n; E[3] = S3;
}

__device__ __forceinline__ void stepS(ull E[4], ull O[4],
                                      ulonglong2 Rlo, ulonglong2 Rhi, float f)
{
    float prev = __shfl_up_sync(FULLM, hix2(O[3]), 1) * f;
    float o3lo = lox2(O[3]);
    ull S3 = addx2(E[3], O[2]); ull T3 = addx2(O[3], S3);
    O[3] = mulx2(Rhi.y, T3); E[3] = S3;
    ull S2 = addx2(E[2], O[1]); ull T2 = addx2(O[2], S2);
    O[2] = mulx2(Rhi.x, T2); E[2] = S2;
    ull S1 = addx2(E[1], O[0]); ull T1 = addx2(O[1], S1);
    O[1] = mulx2(Rlo.y, T1); E[1] = S1;
    ull Osh0 = packx2(prev, o3lo);
    ull S0 = addx2(E[0], Osh0); ull T0 = addx2(O[0], S0);
    O[0] = mulx2(Rlo.x, T0); E[0] = S0;
}

#define FS_RENORM()                                                           \
    do {                                                                      \
        float m = fmaxf(                                                      \
            fmaxf(fmaxf(lox2(E[0]), hix2(E[0])), fmaxf(lox2(E[1]), hix2(E[1]))), \
            fmaxf(fmaxf(lox2(E[2]), hix2(E[2])), fmaxf(lox2(E[3]), hix2(E[3])))); \
        float mo = fmaxf(                                                     \
            fmaxf(fmaxf(lox2(O[0]), hix2(O[0])), fmaxf(lox2(O[1]), hix2(O[1]))), \
            fmaxf(fmaxf(lox2(O[2]), hix2(O[2])), fmaxf(lox2(O[3]), hix2(O[3])))); \
        m = fmaxf(m, mo);                                                     \
        bool nz = (m > 0.f);                                                  \
        if (nz) {                                                             \
            int Ee = (int)((__float_as_uint(m) >> 23) & 255u);                \
            float sc = __uint_as_float((unsigned)(254 - Ee) << 23);           \
            ull SC = packx2(sc, sc);                                          \
            E[0] = mulx2(E[0], SC); E[1] = mulx2(E[1], SC);                   \
            E[2] = mulx2(E[2], SC); E[3] = mulx2(E[3], SC);                   \
            O[0] = mulx2(O[0], SC); O[1] = mulx2(O[1], SC);                   \
            O[2] = mulx2(O[2], SC); O[3] = mulx2(O[3], SC);                   \
            G += Ee - 127;                                                    \
        }                                                                     \
        int val = (G << 1) | (nz ? 1 : 0);                                    \
        int up  = __shfl_up_sync(FULLM, val, 1);                              \
        int Gup = up >> 1;                                                    \
        if (!nz && lane > 0) G = Gup;                                         \
        int D = Gup - G;                                                      \
        if (D > 127) D = 127;                                                 \
        f = (lane == 0 || D < -126) ? 0.f                                     \
            : __uint_as_float((unsigned)(D + 127) << 23);                     \
    } while (0)

#define FS_CAPTURE()                                                          \
    do {                                                                      \
        _Pragma("unroll")                                                     \
        for (int k = 0; k < 8; ++k) {                                         \
            float ek = (k < 4) ? lox2(E[k]) : hix2(E[k - 4]);                 \
            float ok = (k < 4) ? lox2(O[k]) : hix2(O[k - 4]);                 \
            int se_ = 16 * lane + 2 * k;                                      \
            if (se_ == S)     fincap += ek;                                   \
            if (se_ == S - 2) fincap += ok;                                   \
        }                                                                     \
        Gcap = G;                                                             \
    } while (0)

// ---------------------------------------------------------------------------
// Phase 2: one WARP per batch. Streaming via TMA bulk copy -> 4-stage smem
// ring (8 rows / 8KB per stage, mbarrier-tracked, 3 stages in flight).
// Scoreboard-free prefetch; consumption via LDS.128 with 1-row pipeline.
// ---------------------------------------------------------------------------
__global__ void __launch_bounds__(32)
fsloss_scan(const int* __restrict__ text_lens, const int* __restrict__ mel_lens,
            int T, float* __restrict__ out)
{
    __shared__ __align__(128) unsigned char sdat[4 * 8192];
    __shared__ unsigned long long smbar[4];

    const int b = blockIdx.x, lane = threadIdx.x;
    const int tl = text_lens[b], ml = mel_lens[b];
    const int S = 2 * tl, mlm1 = ml - 1;
    const int B = gridDim.x;

    const uint32_t sdat_a = smem_u32(sdat);
    const uint32_t mbar_a = smem_u32(smbar);
    const float* src = g_r + (size_t)b * T * UPAD;

    if (lane == 0) {
        #pragma unroll
        for (int s = 0; s < 4; ++s)
            asm volatile("mbarrier.init.shared.b64 [%0], 1;"
                         :: "r"(mbar_a + 8u * s) : "memory");
    }
    __syncwarp();

    const int full = mlm1 >> 3;          // stages 0..full; main loop 0..full-1
    if (lane == 0) {
        int nfill = (full >= 2) ? 3 : full + 1;
        for (int s = 0; s < nfill; ++s)
            tma_fill(sdat_a + s * 8192u, src + (size_t)s * 2048, mbar_a + 8u * s);
    }

    ull E[4], O[4];
    #pragma unroll
    for (int j = 0; j < 4; ++j) { E[j] = 0ull; O[j] = 0ull; }
    if (lane == 0) E[0] = packx2(1.f, 0.f);

    int   G = 0, Gcap = 0;
    float fincap = 0.f;
    float f = (lane == 0) ? 0.f : 1.f;
    float prevS = 0.f, raw;

    for (int i = 0; i < full; ++i) {
        const int slot = i & 3;
        mbar_wait(mbar_a + 8u * slot, (i >> 2) & 1);
        const uint32_t sb = sdat_a + slot * 8192u + lane * 16u;
        ulonglong2 c0 = lds128(sb), c1 = lds128(sb + 512u);
        #pragma unroll
        for (int r = 0; r < 8; ++r) {
            ulonglong2 n0, n1;
            if (r < 7) {
                n0 = lds128(sb + (r + 1) * 1024u);
                n1 = lds128(sb + (r + 1) * 1024u + 512u);
            }
            stepP(E, O, c0, c1, prevS, raw);
            prevS = raw * f;
            if (r < 7) { c0 = n0; c1 = n1; }
        }
        const int ns = i + 3;
        if (ns <= full && lane == 0)
            tma_fill(sdat_a + (ns & 3) * 8192u, src + (size_t)ns * 2048,
                     mbar_a + 8u * (ns & 3));
        FS_RENORM();
        prevS = __shfl_up_sync(FULLM, hix2(O[3]), 1) * f;   // post-scale refresh
    }

    // tail: steps 8*full .. mlm1 (rem+1 steps, rem in 0..7)
    {
        const int slot = full & 3;
        mbar_wait(mbar_a + 8u * slot, (full >> 2) & 1);
        const uint32_t sb = sdat_a + slot * 8192u + lane * 16u;
        const int rem = mlm1 - 8 * full;
        #pragma unroll
        for (int r = 0; r < 8; ++r) {
            ulonglong2 c0 = lds128(sb + r * 1024u);
            ulonglong2 c1 = lds128(sb + r * 1024u + 512u);
            stepS(E, O, c0, c1, f);
            if (r == rem) { FS_CAPTURE(); break; }
        }
    }

    // epilogue: Zsum = sum_{t<ml} logZ_t  (log c = -ml - Zsum)
    const float* lz = g_logZ + (size_t)b * T;
    double zs = 0.0, zs2 = 0.0;
    int i2 = lane;
    for (; i2 + 32 < ml; i2 += 64) {
        zs  += (double)__ldg(&lz[i2]);
        zs2 += (double)__ldg(&lz[i2 + 32]);
    }
    if (i2 < ml) zs += (double)__ldg(&lz[i2]);
    zs += zs2;
    #pragma unroll
    for (int off = 16; off; off >>= 1)
        zs += __shfl_xor_sync(FULLM, zs, off);

    // lse over lanes (up to 2 lanes hold fin terms with different exponents)
    double lv = (fincap > 0.f)
        ? (log((double)fincap) + (double)Gcap * 0.6931471805599453)
        : -1e300;
    double mx = lv;
    #pragma unroll
    for (int off = 16; off; off >>= 1)
        mx = fmax(mx, __shfl_xor_sync(FULLM, mx, off));
    double ex = (lv > -1e299) ? exp(lv - mx) : 0.0;
    #pragma unroll
    for (int off = 16; off; off >>= 1)
        ex += __shfl_xor_sync(FULLM, ex, off);

    if (lane == 0) {
        float loss = 0.f;
        if (mx > -1e299) {
            double fin = (mx + log(ex)) - (double)ml - zs;
            loss = (float)(-fin / (double)tl);
        }
        g_loss[b] = loss;
        __threadfence();
        int ticket = atomicAdd(&g_done, 1);
        if (ticket == B - 1) {           // last CTA reduces (fixed order)
            float s = 0.f;
            for (int i = 0; i < B; ++i) s += g_loss[i];
            out[0] = s / (float)B;
        }
    }
}

extern "C" void kernel_launch(void* const* d_in, const int* in_sizes, int n_in,
                              void* d_out, int out_size)
{
    const float* attn = (const float*)d_in[0];
    const int*   tl   = (const int*)d_in[1];
    const int*   ml   = (const int*)d_in[2];
    int B = in_sizes[1];
    const int U = 250;
    int T = in_sizes[0] / (B * U);

    int rows = B * T;
    fsloss_prep<<<(rows * 32 + 255) / 256, 256>>>(attn, tl, B, T, U);
    fsloss_scan<<<B, 32>>>(tl, ml, T, (float*)d_out);
}

// round 11
// speedup vs baseline: 1.4399x; 1.1226x over previous
#include <cuda_runtime.h>
#include <math.h>
#include <stdint.h>

#define FULLM 0xffffffffu
#define BMAX 64
#define TMAX 1000
#define UPAD 256
#define STGB 16384u            // 16 rows/stage

typedef unsigned long long ull;

// Scratch (allocation-free rule: __device__ globals).
__device__ float g_loss[BMAX];
__device__ float g_logZ[BMAX * TMAX];
__device__ int   g_done;
__device__ __align__(128) float g_r[(size_t)BMAX * TMAX * UPAD];  // 64 MB

// ---- f32x2 packed helpers (Blackwell sm_103a) ------------------------------
__device__ __forceinline__ ull addx2(ull a, ull b) {
    ull r; asm("add.rn.f32x2 %0, %1, %2;" : "=l"(r) : "l"(a), "l"(b)); return r;
}
__device__ __forceinline__ ull mulx2(ull a, ull b) {
    ull r; asm("mul.rn.f32x2 %0, %1, %2;" : "=l"(r) : "l"(a), "l"(b)); return r;
}
__device__ __forceinline__ ull packx2(float lo, float hi) {
    ull r; asm("mov.b64 %0, {%1, %2};" : "=l"(r) : "f"(lo), "f"(hi)); return r;
}
__device__ __forceinline__ float lox2(ull v) {
    float a, b; asm("mov.b64 {%0, %1}, %2;" : "=f"(a), "=f"(b) : "l"(v)); return a;
}
__device__ __forceinline__ float hix2(ull v) {
    float a, b; asm("mov.b64 {%0, %1}, %2;" : "=f"(a), "=f"(b) : "l"(v)); return b;
}
__device__ __forceinline__ uint32_t smem_u32(const void* p) {
    uint32_t a;
    asm("{.reg .u64 t; cvta.to.shared.u64 t, %1; cvt.u32.u64 %0, t;}"
        : "=r"(a) : "l"(p));
    return a;
}
__device__ __forceinline__ ulonglong2 lds128(uint32_t a) {
    ulonglong2 v;
    asm("ld.shared.v2.u64 {%0, %1}, [%2];" : "=l"(v.x), "=l"(v.y) : "r"(a));
    return v;
}
__device__ __forceinline__ void mbar_wait(uint32_t bar, int parity) {
    asm volatile(
        "{\n\t.reg .pred P;\n"
        "W%=:\n\t"
        "mbarrier.try_wait.parity.shared.b64 P, [%0], %1;\n\t"
        "@!P bra W%=;\n\t}"
        :: "r"(bar), "r"(parity) : "memory");
}
__device__ __forceinline__ void tma_fill(uint32_t dst, const float* src,
                                         uint32_t bar, uint32_t bytes) {
    asm volatile("mbarrier.arrive.expect_tx.shared.b64 _, [%0], %1;"
                 :: "r"(bar), "r"(bytes) : "memory");
    asm volatile(
        "cp.async.bulk.shared::cta.global.mbarrier::complete_tx::bytes "
        "[%0], [%1], %2, [%3];"
        :: "r"(dst), "l"(src), "r"(bytes), "r"(bar) : "memory");
}

// ---------------------------------------------------------------------------
// Phase 1: r[b,t,u] = exp(x+1) (masked for u>=tl); logZ = log1p(sum r) - 1.
// PERMUTED + INTERLEAVED store: [v0,v4,v1,v5] at slot lane, [v2,v6,v3,v7] at
// slot 32+lane (stride-4 pairs for the packed scan).
// ---------------------------------------------------------------------------
__global__ void __launch_bounds__(256)
fsloss_prep(const float* __restrict__ attn, const int* __restrict__ text_lens,
            int B, int T, int U)
{
    if (blockIdx.x == 0 && threadIdx.x == 0) g_done = 0;

    const int gw   = (blockIdx.x * blockDim.x + threadIdx.x) >> 5;
    const int lane = threadIdx.x & 31;
    if (gw >= B * T) return;
    const int b  = gw / T;
    const int tl = text_lens[b];
    const int u0 = 8 * lane;

    const float2* x2 = (const float2*)(attn + (size_t)gw * U) + 4 * lane;
    float v[8];
    #pragma unroll
    for (int j = 0; j < 4; ++j) {
        float2 d = make_float2(0.f, 0.f);
        if (u0 + 2 * j + 1 < U) d = __ldg(&x2[j]);
        v[2 * j]     = d.x;
        v[2 * j + 1] = d.y;
    }
    float s = 0.f;
    #pragma unroll
    for (int k = 0; k < 8; ++k) {
        float e = (u0 + k < tl) ? __expf(v[k] + 1.f) : 0.f;  // r = exp(x+1)
        v[k] = e;
        s += e;
    }
    #pragma unroll
    for (int off = 16; off; off >>= 1) s += __shfl_xor_sync(FULLM, s, off);
    if (lane == 0) g_logZ[gw] = __logf(s + 1.f) - 1.f;

    float4* dst = (float4*)(g_r + (size_t)gw * UPAD);
    dst[lane]      = make_float4(v[0], v[4], v[1], v[5]);
    dst[32 + lane] = make_float4(v[2], v[6], v[3], v[7]);
}

// ---------------------------------------------------------------------------
// Phase 2 step: lane l holds packed pairs E[j]=(e[j],e[j+4]), O[j]=(o[j],o[j+4]).
// Shifted operand (o[j-1],o[j+3]) is exactly O[j-1] for j>=1.
// ---------------------------------------------------------------------------
__device__ __forceinline__ void stepP(ull E[4], ull O[4],
                                      ulonglong2 Rlo, ulonglong2 Rhi,
                                      float prevS, float& rawNext)
{
    float o3lo = lox2(O[3]);
    ull S3 = addx2(E[3], O[2]);
    ull T3 = addx2(O[3], S3);
    ull O3n = mulx2(Rhi.y, T3);
    rawNext = __shfl_up_sync(FULLM, hix2(O3n), 1);   // new o[7] -> next step
    ull S2 = addx2(E[2], O[1]);
    ull T2 = addx2(O[2], S2);
    O[2] = mulx2(Rhi.x, T2); E[2] = S2;
    ull S1 = addx2(E[1], O[0]);
    ull T1 = addx2(O[1], S1);
    O[1] = mulx2(Rlo.y, T1); E[1] = S1;
    ull Osh0 = packx2(prevS, o3lo);                  // prevS consumed last
    ull S0 = addx2(E[0], Osh0);
    ull T0 = addx2(O[0], S0);
    O[0] = mulx2(Rlo.x, T0); E[0] = S0;
    O[3] = O3n; E[3] = S3;
}

__device__ __forceinline__ void stepS(ull E[4], ull O[4],
                                      ulonglong2 Rlo, ulonglong2 Rhi, float f)
{
    float prev = __shfl_up_sync(FULLM, hix2(O[3]), 1) * f;
    float o3lo = lox2(O[3]);
    ull S3 = addx2(E[3], O[2]); ull T3 = addx2(O[3], S3);
    O[3] = mulx2(Rhi.y, T3); E[3] = S3;
    ull S2 = addx2(E[2], O[1]); ull T2 = addx2(O[2], S2);
    O[2] = mulx2(Rhi.x, T2); E[2] = S2;
    ull S1 = addx2(E[1], O[0]); ull T1 = addx2(O[1], S1);
    O[1] = mulx2(Rlo.y, T1); E[1] = S1;
    ull Osh0 = packx2(prev, o3lo);
    ull S0 = addx2(E[0], Osh0); ull T0 = addx2(O[0], S0);
    O[0] = mulx2(Rlo.x, T0); E[0] = S0;
}

// Cheap renorm: exponent taken from the SUM of all 16 non-negative values
// (valid upper bound on the max; overshoot <= 4 exponent bits, harmless).
// Single shfl carries (G<<1)|nz: if the neighbor was zero it exports o7=0,
// so f is don't-care there and is forced to 0 via the nz bit.
#define FS_RENORM()                                                           \
    do {                                                                      \
        ull sE = addx2(addx2(E[0], E[1]), addx2(E[2], E[3]));                 \
        ull sO = addx2(addx2(O[0], O[1]), addx2(O[2], O[3]));                 \
        ull sA = addx2(sE, sO);                                               \
        float msum = lox2(sA) + hix2(sA);                                     \
        bool nz = (msum > 0.f);                                               \
        if (nz) {                                                             \
            int Ee = (int)((__float_as_uint(msum) >> 23) & 255u);             \
            float sc = __uint_as_float((unsigned)(254 - Ee) << 23);           \
            ull SC = packx2(sc, sc);                                          \
            E[0] = mulx2(E[0], SC); E[1] = mulx2(E[1], SC);                   \
            E[2] = mulx2(E[2], SC); E[3] = mulx2(E[3], SC);                   \
            O[0] = mulx2(O[0], SC); O[1] = mulx2(O[1], SC);                   \
            O[2] = mulx2(O[2], SC); O[3] = mulx2(O[3], SC);                   \
            G += Ee - 127;                                                    \
        }                                                                     \
        int val = (G << 1) | (nz ? 1 : 0);                                    \
        int up  = __shfl_up_sync(FULLM, val, 1);                              \
        int Gup = up >> 1;                                                    \
        if (!nz && lane > 0) G = Gup;                                         \
        int D = Gup - G;                                                      \
        if (D > 127) D = 127;                                                 \
        f = (lane == 0 || !(up & 1) || D < -126) ? 0.f                        \
            : __uint_as_float((unsigned)(D + 127) << 23);                     \
    } while (0)

#define FS_CAPTURE()                                                          \
    do {                                                                      \
        _Pragma("unroll")                                                     \
        for (int k = 0; k < 8; ++k) {                                         \
            float ek = (k < 4) ? lox2(E[k]) : hix2(E[k - 4]);                 \
            float ok = (k < 4) ? lox2(O[k]) : hix2(O[k - 4]);                 \
            int se_ = 16 * lane + 2 * k;                                      \
            if (se_ == S)     fincap += ek;                                   \
            if (se_ == S - 2) fincap += ok;                                   \
        }                                                                     \
        Gcap = G;                                                             \
    } while (0)

// ---------------------------------------------------------------------------
// Phase 2: one WARP per batch. TMA -> 4-stage x 16KB smem ring (16 rows per
// stage, mbarrier-tracked, 3 in flight). Renorm every 8 steps.
// ---------------------------------------------------------------------------
__global__ void __launch_bounds__(32)
fsloss_scan(const int* __restrict__ text_lens, const int* __restrict__ mel_lens,
            int T, float* __restrict__ out)
{
    __shared__ __align__(128) unsigned char sdat[4 * STGB];
    __shared__ unsigned long long smbar[4];

    const int b = blockIdx.x, lane = threadIdx.x;
    const int tl = text_lens[b], ml = mel_lens[b];
    const int S = 2 * tl, mlm1 = ml - 1;
    const int B = gridDim.x;

    const uint32_t sdat_a = smem_u32(sdat);
    const uint32_t mbar_a = smem_u32(smbar);
    const float* src = g_r + (size_t)b * T * UPAD;

    if (lane == 0) {
        #pragma unroll
        for (int s = 0; s < 4; ++s)
            asm volatile("mbarrier.init.shared.b64 [%0], 1;"
                         :: "r"(mbar_a + 8u * s) : "memory");
    }
    __syncwarp();

    const int full = mlm1 >> 4;          // 16-step superblocks; tail in stage full
    if (lane == 0) {
        int nfill = (full >= 2) ? 3 : full + 1;
        for (int s = 0; s < nfill; ++s) {
            int rb = 16 * s; if (rb > T - 16) rb = T - 16;
            tma_fill(sdat_a + s * STGB, src + (size_t)rb * UPAD,
                     mbar_a + 8u * s, STGB);
        }
    }

    ull E[4], O[4];
    #pragma unroll
    for (int j = 0; j < 4; ++j) { E[j] = 0ull; O[j] = 0ull; }
    if (lane == 0) E[0] = packx2(1.f, 0.f);

    int   G = 0, Gcap = 0;
    float fincap = 0.f;
    float f = (lane == 0) ? 0.f : 1.f;
    float prevS = 0.f, raw;

    for (int i = 0; i < full; ++i) {
        const int slot = i & 3;
        mbar_wait(mbar_a + 8u * slot, (i >> 2) & 1);
        const int ns = i + 3;
        if (ns <= full && lane == 0) {
            int rb = 16 * ns; if (rb > T - 16) rb = T - 16;
            tma_fill(sdat_a + (ns & 3) * STGB, src + (size_t)rb * UPAD,
                     mbar_a + 8u * (ns & 3), STGB);
        }
        const uint32_t sb = sdat_a + slot * STGB + lane * 16u;
        ulonglong2 c0 = lds128(sb), c1 = lds128(sb + 512u);
        #pragma unroll
        for (int r = 0; r < 16; ++r) {
            ulonglong2 n0, n1;
            if (r < 15) {
                n0 = lds128(sb + (r + 1) * 1024u);
                n1 = lds128(sb + (r + 1) * 1024u + 512u);
            }
            stepP(E, O, c0, c1, prevS, raw);
            prevS = raw * f;
            if (r == 7) {
                FS_RENORM();
                prevS = __shfl_up_sync(FULLM, hix2(O[3]), 1) * f;
            }
            if (r < 15) { c0 = n0; c1 = n1; }
        }
        FS_RENORM();
        prevS = __shfl_up_sync(FULLM, hix2(O[3]), 1) * f;
    }

    // tail: steps 16*full .. mlm1 (rem+1 steps, rem in 0..15)
    {
        const int slot = full & 3;
        mbar_wait(mbar_a + 8u * slot, (full >> 2) & 1);
        int tbase = 16 * full; if (tbase > T - 16) tbase = T - 16;
        const int off0 = 16 * full - tbase;         // 0, or 8 when clamped
        const uint32_t sb = sdat_a + slot * STGB + off0 * 1024u + lane * 16u;
        const int rem = mlm1 - 16 * full;
        #pragma unroll
        for (int r = 0; r < 16; ++r) {
            ulonglong2 c0 = lds128(sb + r * 1024u);
            ulonglong2 c1 = lds128(sb + r * 1024u + 512u);
            stepS(E, O, c0, c1, f);
            if (r == rem) { FS_CAPTURE(); break; }
            if (r == 7) FS_RENORM();
        }
    }

    // epilogue: Zsum = sum_{t<ml} logZ_t  (log c = -ml - Zsum)
    const float* lz = g_logZ + (size_t)b * T;
    double zs = 0.0, zs2 = 0.0;
    int i2 = lane;
    for (; i2 + 32 < ml; i2 += 64) {
        zs  += (double)__ldg(&lz[i2]);
        zs2 += (double)__ldg(&lz[i2 + 32]);
    }
    if (i2 < ml) zs += (double)__ldg(&lz[i2]);
    zs += zs2;
    #pragma unroll
    for (int off = 16; off; off >>= 1)
        zs += __shfl_xor_sync(FULLM, zs, off);

    // lse over lanes (up to 2 lanes hold fin terms with different exponents)
    double lv = (fincap > 0.f)
        ? (log((double)fincap) + (double)Gcap * 0.6931471805599453)
        : -1e300;
    double mx = lv;
    #pragma unroll
    for (int off = 16; off; off >>= 1)
        mx = fmax(mx, __shfl_xor_sync(FULLM, mx, off));
    double ex = (lv > -1e299) ? exp(lv - mx) : 0.0;
    #pragma unroll
    for (int off = 16; off; off >>= 1)
        ex += __shfl_xor_sync(FULLM, ex, off);

    if (lane == 0) {
        float loss = 0.f;
        if (mx > -1e299) {
            double fin = (mx + log(ex)) - (double)ml - zs;
            loss = (float)(-fin / (double)tl);
        }
        g_loss[b] = loss;
        __threadfence();
        int ticket = atomicAdd(&g_done, 1);
        if (ticket == B - 1) {           // last CTA reduces (fixed order)
            float s = 0.f;
            for (int i = 0; i < B; ++i) s += g_loss[i];
            out[0] = s / (float)B;
        }
    }
}

extern "C" void kernel_launch(void* const* d_in, const int* in_sizes, int n_in,
                              void* d_out, int out_size)
{
    const float* attn = (const float*)d_in[0];
    const int*   tl   = (const int*)d_in[1];
    const int*   ml   = (const int*)d_in[2];
    int B = in_sizes[1];
    const int U = 250;
    int T = in_sizes[0] / (B * U);

    int rows = B * T;
    fsloss_prep<<<(rows * 32 + 255) / 256, 256>>>(attn, tl, B, T, U);
    fsloss_scan<<<B, 32>>>(tl, ml, T, (float*)d_out);
}